// round 11
// baseline (speedup 1.0000x reference)
#include <cuda_runtime.h>
#include <cuda_fp16.h>
#include <math_constants.h>

#define NN 50000
#define EE 800000
#define CC 128
#define GG 128
#define L0 512
#define L1 256

#define N4 (NN / 4)                 // 12500 int4 elements (NN divisible by 4)
#define FILL_BLKS ((EE + 255) / 256)            // 3125
#define G0_BLKS   ((NN * 512) / 256)            // 100000

// ---------------- scratch (static device globals; no allocation) ----------------
// NOTE: g_cnt relies on static zero-init for the FIRST execution; k_scan2
// re-zeroes it after consuming, so every graph replay sees zeros again.
__device__ float  g_q[(size_t)NN * CC];       // q per node (f32)
__device__ float  g_s[(size_t)NN * CC];       // skip (x@Ws+bs) per node (f32)
__device__ __half g_kvh[(size_t)NN * 256];    // k(128)|v(128) per node (f16)
__device__ float  g_hA[(size_t)NN * CC];
__device__ float  g_hB[(size_t)NN * CC];
__device__ int    g_cnt[NN];
__device__ int    g_off[NN + 4];              // padded for int4 store
__device__ int    g_cur[NN + 4];
__device__ int    g_srcA[EE];
__device__ float4 g_eaC[EE];                  // edge_attr in CSR order (w unused)
__device__ int    g_gstart[GG + 1];
__device__ float  g_pool[GG * CC];
__device__ float  g_m1[GG * L0];
__device__ float  g_m2[GG * L1];

// ---------------- packed f32x2 helpers ----------------
__device__ __forceinline__ unsigned long long rep2(float x) {
    unsigned long long r;
    asm("mov.b64 %0, {%1, %1};" : "=l"(r) : "f"(x));
    return r;
}
#define FFMA_X2(acc, a, b) asm("fma.rn.f32x2 %0, %1, %2, %0;" : "+l"(acc) : "l"(a), "l"(b))

union U64F2 { unsigned long long u; float2 f; };

// ---------------- CSR build ----------------
__global__ void k_count(const int* __restrict__ ei) {
    int e = blockIdx.x * blockDim.x + threadIdx.x;
    if (e < EE) atomicAdd(&g_cnt[ei[EE + e]], 1);
}

// single-launch scan: g_cnt -> g_off/g_cur (exclusive), zero g_cnt, gstart.
// 1024 threads, 13 int4 contiguous chunk per thread, two passes over chunk.
__global__ __launch_bounds__(1024) void k_scan2(const int* __restrict__ batch) {
    const int T = 1024;
    const int CH = 13;
    __shared__ int sh[T];
    int t = threadIdx.x;
    int base = t * CH;

    // pass 1: chunk sum
    int s = 0;
#pragma unroll
    for (int j = 0; j < CH; j++) {
        int idx = base + j;
        if (idx < N4) {
            int4 c = *(const int4*)&g_cnt[idx * 4];
            s += c.x + c.y + c.z + c.w;
        }
    }
    sh[t] = s;
    __syncthreads();
    // inclusive block scan
    for (int d = 1; d < T; d <<= 1) {
        int v = (t >= d) ? sh[t - d] : 0;
        __syncthreads();
        sh[t] += v;
        __syncthreads();
    }
    int run = sh[t] - s;   // exclusive prefix of this chunk

    // pass 2: per-element prefix, store off/cur, zero cnt
    const int4 z = make_int4(0, 0, 0, 0);
#pragma unroll
    for (int j = 0; j < CH; j++) {
        int idx = base + j;
        if (idx < N4) {
            int4 c = *(const int4*)&g_cnt[idx * 4];
            int4 o;
            o.x = run;
            o.y = run + c.x;
            o.z = o.y + c.y;
            o.w = o.z + c.z;
            run = o.w + c.w;
            *(int4*)&g_off[idx * 4] = o;
            *(int4*)&g_cur[idx * 4] = o;
            *(int4*)&g_cnt[idx * 4] = z;     // self-clean for next replay
        }
    }
    if (t == T - 1) g_off[NN] = sh[T - 1];

    // gstart[g] = lower_bound(batch, g)
    if (t <= GG) {
        int lo = 0, hi = NN;
        while (lo < hi) {
            int mid = (lo + hi) >> 1;
            if (batch[mid] < t) lo = mid + 1; else hi = mid;
        }
        g_gstart[t] = lo;
    }
}

// ---------------- fused: CSR fill + layer-0 projection ----------------
__global__ void k_prep(const int* __restrict__ ei, const float* __restrict__ ea,
                       const float* __restrict__ x,
                       const float* __restrict__ Wq, const float* __restrict__ bq,
                       const float* __restrict__ Wk, const float* __restrict__ bk,
                       const float* __restrict__ Wv, const float* __restrict__ bv,
                       const float* __restrict__ Ws, const float* __restrict__ bs) {
    if (blockIdx.x < FILL_BLKS) {
        int e = blockIdx.x * 256 + threadIdx.x;
        if (e < EE) {
            int d = ei[EE + e];
            int p = atomicAdd(&g_cur[d], 1);
            g_srcA[p] = ei[e];
            float4 v;
            v.x = ea[e * 3 + 0]; v.y = ea[e * 3 + 1]; v.z = ea[e * 3 + 2]; v.w = 0.f;
            g_eaC[p] = v;
        }
    } else {
        long long idx = (long long)(blockIdx.x - FILL_BLKS) * 256 + threadIdx.x;
        if (idx >= (long long)NN * 512) return;
        int n = (int)(idx >> 9);
        int col = (int)(idx & 511);
        int grp = col >> 7;
        int c = col & 127;
        const float* W; const float* b;
        if      (grp == 0) { W = Wq; b = bq; }
        else if (grp == 1) { W = Wk; b = bk; }
        else if (grp == 2) { W = Wv; b = bv; }
        else               { W = Ws; b = bs; }
        float x0 = x[n * 4 + 0], x1 = x[n * 4 + 1], x2 = x[n * 4 + 2], x3 = x[n * 4 + 3];
        float v = b[c] + x0 * W[c] + x1 * W[128 + c] + x2 * W[256 + c] + x3 * W[384 + c];
        if      (grp == 0) g_q[(size_t)n * CC + c] = v;
        else if (grp == 1) g_kvh[(size_t)n * 256 + c] = __float2half_rn(v);
        else if (grp == 2) g_kvh[(size_t)n * 256 + 128 + c] = __float2half_rn(v);
        else               g_s[(size_t)n * CC + c] = v;
    }
}

// ---------------- main projection GEMM: [NN,128] @ [128,128] x4 groups ----------------
// 128x128 tile, 512 threads, 8x4 microtile, BK=16, packed f32x2 FMA (M-pairs)
#define AS_STRIDE 132
__global__ __launch_bounds__(512) void k_gemm(int inSel,
                        const float* __restrict__ Wq, const float* __restrict__ bq,
                        const float* __restrict__ Wk, const float* __restrict__ bk,
                        const float* __restrict__ Wv, const float* __restrict__ bv,
                        const float* __restrict__ Ws, const float* __restrict__ bs) {
    const float* __restrict__ H = inSel ? g_hB : g_hA;
    __shared__ __align__(16) float As[16 * AS_STRIDE];  // [k][m], m=0..127
    __shared__ __align__(16) float Bs[16 * 128];        // [k][n], n=0..127

    int tid = threadIdx.x;
    int tx = tid & 31;          // 32 col groups of 4
    int ty = tid >> 5;          // 16 row groups of 8 (warp-uniform!)
    int row0 = blockIdx.y * 128;
    int grp = blockIdx.x;       // 0..3 : q,k,v,s
    const float* W; const float* b;
    if      (grp == 0) { W = Wq; b = bq; }
    else if (grp == 1) { W = Wk; b = bk; }
    else if (grp == 2) { W = Wv; b = bv; }
    else               { W = Ws; b = bs; }

    unsigned long long acc[4][4];
#pragma unroll
    for (int i = 0; i < 4; i++)
#pragma unroll
        for (int j = 0; j < 4; j++) acc[i][j] = 0ULL;

    int am = tid >> 2;            // 0..127 row within tile
    int ak = (tid & 3) * 4;       // k offset (float4)
    int bkL = tid >> 5;           // 0..15
    int bnL = (tid & 31) * 4;     // 0..124

    for (int kk = 0; kk < 128; kk += 16) {
        float4 a4;
        if (row0 + am < NN)
            a4 = *(const float4*)&H[(size_t)(row0 + am) * 128 + kk + ak];
        else
            a4 = make_float4(0.f, 0.f, 0.f, 0.f);
        As[(ak + 0) * AS_STRIDE + am] = a4.x;
        As[(ak + 1) * AS_STRIDE + am] = a4.y;
        As[(ak + 2) * AS_STRIDE + am] = a4.z;
        As[(ak + 3) * AS_STRIDE + am] = a4.w;
        *(float4*)&Bs[bkL * 128 + bnL] = *(const float4*)&W[(size_t)(kk + bkL) * 128 + bnL];
        __syncthreads();
#pragma unroll
        for (int k = 0; k < 16; k++) {
            ulonglong2 a01 = *(const ulonglong2*)&As[k * AS_STRIDE + ty * 8];
            ulonglong2 a23 = *(const ulonglong2*)&As[k * AS_STRIDE + ty * 8 + 4];
            float4 b4 = *(const float4*)&Bs[k * 128 + tx * 4];
            unsigned long long ap[4] = {a01.x, a01.y, a23.x, a23.y};
            unsigned long long br[4] = {rep2(b4.x), rep2(b4.y), rep2(b4.z), rep2(b4.w)};
#pragma unroll
            for (int ip = 0; ip < 4; ip++)
#pragma unroll
                for (int j = 0; j < 4; j++) FFMA_X2(acc[ip][j], ap[ip], br[j]);
        }
        __syncthreads();
    }

    float4 bias = *(const float4*)&b[tx * 4];
    float bb[4] = {bias.x, bias.y, bias.z, bias.w};
#pragma unroll
    for (int ip = 0; ip < 4; ip++) {
        U64F2 c0, c1, c2, c3;
        c0.u = acc[ip][0]; c1.u = acc[ip][1]; c2.u = acc[ip][2]; c3.u = acc[ip][3];
#pragma unroll
        for (int half = 0; half < 2; half++) {
            int r = row0 + ty * 8 + 2 * ip + half;
            if (r >= NN) continue;
            float4 o;
            if (half == 0) {
                o.x = c0.f.x + bb[0]; o.y = c1.f.x + bb[1];
                o.z = c2.f.x + bb[2]; o.w = c3.f.x + bb[3];
            } else {
                o.x = c0.f.y + bb[0]; o.y = c1.f.y + bb[1];
                o.z = c2.f.y + bb[2]; o.w = c3.f.y + bb[3];
            }
            if (grp == 0) {
                *(float4*)&g_q[(size_t)r * CC + tx * 4] = o;
            } else if (grp == 3) {
                *(float4*)&g_s[(size_t)r * CC + tx * 4] = o;
            } else {
                __half2 h0 = __floats2half2_rn(o.x, o.y);
                __half2 h1 = __floats2half2_rn(o.z, o.w);
                uint2 u;
                u.x = *(unsigned int*)&h0;
                u.y = *(unsigned int*)&h1;
                size_t off = (size_t)r * 256 + (grp == 2 ? 128 : 0) + tx * 4;
                *(uint2*)&g_kvh[off] = u;
            }
        }
    }
}

// ---------------- edge aggregation: warp per dst node, online softmax ----------------
// e = We.ea factorization; 2-edge unroll; fp16 k/v gathers.
__device__ __forceinline__ float4 ld_kv4(const __half* base, int idx) {
    uint2 u = *(const uint2*)(base + idx);
    __half2 h0 = *(__half2*)&u.x;
    __half2 h1 = *(__half2*)&u.y;
    float2 f0 = __half22float2(h0);
    float2 f1 = __half22float2(h1);
    return make_float4(f0.x, f0.y, f1.x, f1.y);
}

__global__ __launch_bounds__(256) void k_agg(const float* __restrict__ We,
                                             int outSel) {
    __shared__ float sWe[384];
    for (int i = threadIdx.x; i < 384; i += 256) sWe[i] = We[i];
    __syncthreads();

    int node = blockIdx.x * 8 + (threadIdx.x >> 5);
    if (node >= NN) return;
    int lane = threadIdx.x & 31;

    float4 qv = *(const float4*)&g_q[(size_t)node * CC + lane * 4];

    // t = We . q  (3 scalars, warp-reduced)
    float t0, t1, t2;
    {
        int c = lane * 4;
        t0 = sWe[c] * qv.x + sWe[c + 1] * qv.y + sWe[c + 2] * qv.z + sWe[c + 3] * qv.w;
        c += 128;
        t1 = sWe[c] * qv.x + sWe[c + 1] * qv.y + sWe[c + 2] * qv.z + sWe[c + 3] * qv.w;
        c += 128;
        t2 = sWe[c] * qv.x + sWe[c + 1] * qv.y + sWe[c + 2] * qv.z + sWe[c + 3] * qv.w;
#pragma unroll
        for (int o = 16; o > 0; o >>= 1) {
            t0 += __shfl_xor_sync(0xffffffffu, t0, o);
            t1 += __shfl_xor_sync(0xffffffffu, t1, o);
            t2 += __shfl_xor_sync(0xffffffffu, t2, o);
        }
    }

    float m = -CUDART_INF_F, den = 0.f;
    float4 acc = make_float4(0.f, 0.f, 0.f, 0.f);
    float s0 = 0.f, s1 = 0.f, s2 = 0.f;
    const float scale = 0.08838834764831845f; // 1/sqrt(128)

    int beg = __ldg(&g_off[node]), end = __ldg(&g_off[node + 1]);
    int p = beg;
    for (; p + 2 <= end; p += 2) {
        int n0 = __ldg(&g_srcA[p]), n1 = __ldg(&g_srcA[p + 1]);
        float4 ea0 = g_eaC[p], ea1 = g_eaC[p + 1];
        const __half* b0 = &g_kvh[(size_t)n0 * 256];
        const __half* b1 = &g_kvh[(size_t)n1 * 256];
        float4 kv0 = ld_kv4(b0, lane * 4);
        float4 vv0 = ld_kv4(b0, 128 + lane * 4);
        float4 kv1 = ld_kv4(b1, lane * 4);
        float4 vv1 = ld_kv4(b1, 128 + lane * 4);
        float d0 = qv.x * kv0.x + qv.y * kv0.y + qv.z * kv0.z + qv.w * kv0.w;
        float d1 = qv.x * kv1.x + qv.y * kv1.y + qv.z * kv1.z + qv.w * kv1.w;
#pragma unroll
        for (int o = 16; o > 0; o >>= 1) {
            d0 += __shfl_xor_sync(0xffffffffu, d0, o);
            d1 += __shfl_xor_sync(0xffffffffu, d1, o);
        }
        float l0 = (d0 + ea0.x * t0 + ea0.y * t1 + ea0.z * t2) * scale;
        float l1 = (d1 + ea1.x * t0 + ea1.y * t1 + ea1.z * t2) * scale;
        float nm = fmaxf(m, fmaxf(l0, l1));
        float corr = __expf(m - nm);
        float w0 = __expf(l0 - nm);
        float w1 = __expf(l1 - nm);
        den = den * corr + w0 + w1;
        acc.x = acc.x * corr + w0 * vv0.x + w1 * vv1.x;
        acc.y = acc.y * corr + w0 * vv0.y + w1 * vv1.y;
        acc.z = acc.z * corr + w0 * vv0.z + w1 * vv1.z;
        acc.w = acc.w * corr + w0 * vv0.w + w1 * vv1.w;
        s0 = s0 * corr + w0 * ea0.x + w1 * ea1.x;
        s1 = s1 * corr + w0 * ea0.y + w1 * ea1.y;
        s2 = s2 * corr + w0 * ea0.z + w1 * ea1.z;
        m = nm;
    }
    if (p < end) {
        int n0 = __ldg(&g_srcA[p]);
        float4 ea0 = g_eaC[p];
        const __half* b0 = &g_kvh[(size_t)n0 * 256];
        float4 kv0 = ld_kv4(b0, lane * 4);
        float4 vv0 = ld_kv4(b0, 128 + lane * 4);
        float d0 = qv.x * kv0.x + qv.y * kv0.y + qv.z * kv0.z + qv.w * kv0.w;
#pragma unroll
        for (int o = 16; o > 0; o >>= 1) d0 += __shfl_xor_sync(0xffffffffu, d0, o);
        float l0 = (d0 + ea0.x * t0 + ea0.y * t1 + ea0.z * t2) * scale;
        float nm = fmaxf(m, l0);
        float corr = __expf(m - nm);
        float w0 = __expf(l0 - nm);
        den = den * corr + w0;
        acc.x = acc.x * corr + w0 * vv0.x;
        acc.y = acc.y * corr + w0 * vv0.y;
        acc.z = acc.z * corr + w0 * vv0.z;
        acc.w = acc.w * corr + w0 * vv0.w;
        s0 = s0 * corr + w0 * ea0.x;
        s1 = s1 * corr + w0 * ea0.y;
        s2 = s2 * corr + w0 * ea0.z;
        m = nm;
    }

    float inv = den > 0.f ? 1.f / den : 0.f;
    s0 *= inv; s1 *= inv; s2 *= inv;
    float4 skip = *(const float4*)&g_s[(size_t)node * CC + lane * 4];
    int c = lane * 4;
    float4 o;
    o.x = acc.x * inv + s0 * sWe[c + 0] + s1 * sWe[128 + c + 0] + s2 * sWe[256 + c + 0] + skip.x;
    o.y = acc.y * inv + s0 * sWe[c + 1] + s1 * sWe[128 + c + 1] + s2 * sWe[256 + c + 1] + skip.y;
    o.z = acc.z * inv + s0 * sWe[c + 2] + s1 * sWe[128 + c + 2] + s2 * sWe[256 + c + 2] + skip.z;
    o.w = acc.w * inv + s0 * sWe[c + 3] + s1 * sWe[128 + c + 3] + s2 * sWe[256 + c + 3] + skip.w;
    o.x = o.x > 0.f ? o.x : 0.01f * o.x;
    o.y = o.y > 0.f ? o.y : 0.01f * o.y;
    o.z = o.z > 0.f ? o.z : 0.01f * o.z;
    o.w = o.w > 0.f ? o.w : 0.01f * o.w;
    float* __restrict__ out = outSel ? g_hB : g_hA;
    *(float4*)&out[(size_t)node * CC + c] = o;
}

// ---------------- pooling: batch is sorted -> segmented sum, no atomics ----------------
__global__ void k_pool(int hSel) {
    int g = blockIdx.x;       // graph
    int c = threadIdx.x;      // channel
    const float* h = hSel ? g_hB : g_hA;
    int s = g_gstart[g], e = g_gstart[g + 1];
    float acc = 0.f;
    for (int n = s; n < e; n++) acc += h[(size_t)n * CC + c];
    g_pool[g * CC + c] = acc;
}

// ---------------- MLP head ----------------
__global__ void k_mlp1(const float* __restrict__ W, const float* __restrict__ b) {
    int idx = blockIdx.x * blockDim.x + threadIdx.x;
    if (idx >= GG * L0) return;
    int r = idx >> 9, c = idx & (L0 - 1);
    float s = b[c];
    for (int k = 0; k < CC; k++) s += g_pool[r * CC + k] * W[k * L0 + c];
    g_m1[idx] = s > 0.f ? s : 0.f;
}

__global__ void k_mlp2(const float* __restrict__ W, const float* __restrict__ b) {
    int idx = blockIdx.x * blockDim.x + threadIdx.x;
    if (idx >= GG * L1) return;
    int r = idx >> 8, c = idx & (L1 - 1);
    float s = b[c];
    for (int k = 0; k < L0; k++) s += g_m1[r * L0 + k] * W[k * L1 + c];
    g_m2[idx] = s > 0.f ? s : 0.f;
}

__global__ void k_mlp3(const float* __restrict__ W, const float* __restrict__ b,
                       float* __restrict__ out) {
    int idx = threadIdx.x;
    if (idx >= GG * 2) return;
    int r = idx >> 1, c = idx & 1;
    float s = b[c];
    for (int k = 0; k < L1; k++) s += g_m2[r * L1 + k] * W[k * 2 + c];
    out[idx] = s;
}

// ---------------- launch ----------------
extern "C" void kernel_launch(void* const* d_in, const int* in_sizes, int n_in,
                              void* d_out, int out_size) {
    const float* x     = (const float*)d_in[0];
    const int*   ei    = (const int*)d_in[1];
    const float* ea    = (const float*)d_in[2];
    const int*   batch = (const int*)d_in[3];
    const float* Wq0 = (const float*)d_in[4];  const float* bq0 = (const float*)d_in[5];
    const float* Wk0 = (const float*)d_in[6];  const float* bk0 = (const float*)d_in[7];
    const float* Wv0 = (const float*)d_in[8];  const float* bv0 = (const float*)d_in[9];
    const float* We0 = (const float*)d_in[10];
    const float* Ws0 = (const float*)d_in[11]; const float* bs0 = (const float*)d_in[12];
    const float* Wq1 = (const float*)d_in[13]; const float* bq1 = (const float*)d_in[14];
    const float* Wk1 = (const float*)d_in[15]; const float* bk1 = (const float*)d_in[16];
    const float* Wv1 = (const float*)d_in[17]; const float* bv1 = (const float*)d_in[18];
    const float* We1 = (const float*)d_in[19];
    const float* Ws1 = (const float*)d_in[20]; const float* bs1 = (const float*)d_in[21];
    const float* Wl0 = (const float*)d_in[22]; const float* bl0 = (const float*)d_in[23];
    const float* Wl1 = (const float*)d_in[24]; const float* bl1 = (const float*)d_in[25];
    const float* Wl2 = (const float*)d_in[26]; const float* bl2 = (const float*)d_in[27];
    float* out = (float*)d_out;

    // CSR build: count -> scan(+zero cnt, +gstart) -> fill (fused with layer-0 proj)
    k_count<<<(EE + 255) / 256, 256>>>(ei);
    k_scan2<<<1, 1024>>>(batch);
    k_prep<<<FILL_BLKS + G0_BLKS, 256>>>(ei, ea, x,
                                         Wq0, bq0, Wk0, bk0, Wv0, bv0, Ws0, bs0);

    dim3 gemmGrid(4, (NN + 127) / 128);

    // layer 0 aggregation (this is launch #4 -> ncu profiles it)
    k_agg<<<(NN + 7) / 8, 256>>>(We0, 0);              // -> hA
    // layer 1 (shared weights)
    k_gemm<<<gemmGrid, 512>>>(0, Wq1, bq1, Wk1, bk1, Wv1, bv1, Ws1, bs1);
    k_agg<<<(NN + 7) / 8, 256>>>(We1, 1);              // -> hB
    // layer 2 (same weights)
    k_gemm<<<gemmGrid, 512>>>(1, Wq1, bq1, Wk1, bk1, Wv1, bv1, Ws1, bs1);
    k_agg<<<(NN + 7) / 8, 256>>>(We1, 0);              // -> hA

    // global add pool (segmented, batch sorted)
    k_pool<<<GG, CC>>>(0);

    // MLP head
    k_mlp1<<<(GG * L0 + 255) / 256, 256>>>(Wl0, bl0);
    k_mlp2<<<(GG * L1 + 255) / 256, 256>>>(Wl1, bl1);
    k_mlp3<<<1, 256>>>(Wl2, bl2, out);
}

// round 12
// speedup vs baseline: 1.0162x; 1.0162x over previous
#include <cuda_runtime.h>
#include <cuda_fp16.h>
#include <math_constants.h>

#define NN 50000
#define EE 800000
#define CC 128
#define GG 128
#define L0 512
#define L1 256

#define N4 (NN / 4)                 // 12500 int4 elements
#define SCAN_BLK 256
#define SCAN_NBLK ((N4 + SCAN_BLK - 1) / SCAN_BLK)   // 49
#define FILL_BLKS ((EE + 255) / 256)            // 3125
#define G0_BLKS   ((NN * 512) / 256)            // 100000

// ---------------- scratch (static device globals; no allocation) ----------------
__device__ float  g_q[(size_t)NN * CC];       // q per node (f32)
__device__ float  g_s[(size_t)NN * CC];       // skip (x@Ws+bs) per node (f32)
__device__ __half g_kvh[(size_t)NN * 256];    // k(128)|v(128) per node (f16)
__device__ float  g_hA[(size_t)NN * CC];
__device__ float  g_hB[(size_t)NN * CC];
__device__ int    g_cnt[NN];
__device__ int    g_off[NN + 4];              // padded for int4 store
__device__ int    g_cur[NN + 4];
__device__ int    g_bsum[SCAN_NBLK];
__device__ int    g_srcA[EE];
__device__ float4 g_eaC[EE];                  // edge_attr in CSR order (w unused)
__device__ int    g_gstart[GG + 1];
__device__ float  g_pool[GG * CC];
__device__ float  g_m1[GG * L0];
__device__ float  g_m2[GG * L1];

// ---------------- packed f32x2 helpers ----------------
__device__ __forceinline__ unsigned long long rep2(float x) {
    unsigned long long r;
    asm("mov.b64 %0, {%1, %1};" : "=l"(r) : "f"(x));
    return r;
}
#define FFMA_X2(acc, a, b) asm("fma.rn.f32x2 %0, %1, %2, %0;" : "+l"(acc) : "l"(a), "l"(b))

union U64F2 { unsigned long long u; float2 f; };

// ---------------- CSR build ----------------
__global__ void k_zero() {
    int i = blockIdx.x * blockDim.x + threadIdx.x;
    if (i < NN) g_cnt[i] = 0;
}

__global__ void k_count(const int* __restrict__ ei) {
    int e = blockIdx.x * blockDim.x + threadIdx.x;
    if (e < EE) atomicAdd(&g_cnt[ei[EE + e]], 1);
}

__global__ void k_sum() {
    __shared__ int sh[SCAN_BLK];
    int t = threadIdx.x;
    int i4 = blockIdx.x * SCAN_BLK + t;
    int s = 0;
    if (i4 < N4) {
        int4 c = *(const int4*)&g_cnt[i4 * 4];
        s = c.x + c.y + c.z + c.w;
    }
    sh[t] = s;
    __syncthreads();
    for (int d = SCAN_BLK / 2; d > 0; d >>= 1) {
        if (t < d) sh[t] += sh[t + d];
        __syncthreads();
    }
    if (t == 0) g_bsum[blockIdx.x] = sh[0];
}

// scat with inlined block-sum scan; also computes gstart (binary search)
__global__ void k_scat(const int* __restrict__ batch) {
    __shared__ int sh[SCAN_BLK];
    __shared__ int bpre[SCAN_NBLK + 1];
    int t = threadIdx.x;
    if (t < SCAN_NBLK) bpre[t] = g_bsum[t];
    __syncthreads();
    if (t == 0) {
        int run = 0;
        for (int i = 0; i < SCAN_NBLK; i++) { int v = bpre[i]; bpre[i] = run; run += v; }
        bpre[SCAN_NBLK] = run;
    }
    __syncthreads();

    int i4 = blockIdx.x * SCAN_BLK + t;
    int4 c = make_int4(0, 0, 0, 0);
    if (i4 < N4) c = *(const int4*)&g_cnt[i4 * 4];
    int s = c.x + c.y + c.z + c.w;
    sh[t] = s;
    __syncthreads();
    for (int d = 1; d < SCAN_BLK; d <<= 1) {
        int u = (t >= d) ? sh[t - d] : 0;
        __syncthreads();
        sh[t] += u;
        __syncthreads();
    }
    if (i4 < N4) {
        int base = bpre[blockIdx.x] + sh[t] - s;
        int4 o;
        o.x = base;
        o.y = base + c.x;
        o.z = o.y + c.y;
        o.w = o.z + c.z;
        *(int4*)&g_off[i4 * 4] = o;
        *(int4*)&g_cur[i4 * 4] = o;
    }
    if (blockIdx.x == 0) {
        if (t == 0) g_off[NN] = bpre[SCAN_NBLK];
        if (t <= GG) {
            int lo = 0, hi = NN;
            while (lo < hi) {
                int mid = (lo + hi) >> 1;
                if (batch[mid] < t) lo = mid + 1; else hi = mid;
            }
            g_gstart[t] = lo;
        }
    }
}

// ---------------- fused: CSR fill + layer-0 projection ----------------
__global__ void k_prep(const int* __restrict__ ei, const float* __restrict__ ea,
                       const float* __restrict__ x,
                       const float* __restrict__ Wq, const float* __restrict__ bq,
                       const float* __restrict__ Wk, const float* __restrict__ bk,
                       const float* __restrict__ Wv, const float* __restrict__ bv,
                       const float* __restrict__ Ws, const float* __restrict__ bs) {
    if (blockIdx.x < FILL_BLKS) {
        int e = blockIdx.x * 256 + threadIdx.x;
        if (e < EE) {
            int d = ei[EE + e];
            int p = atomicAdd(&g_cur[d], 1);
            g_srcA[p] = ei[e];
            float4 v;
            v.x = ea[e * 3 + 0]; v.y = ea[e * 3 + 1]; v.z = ea[e * 3 + 2]; v.w = 0.f;
            g_eaC[p] = v;
        }
    } else {
        long long idx = (long long)(blockIdx.x - FILL_BLKS) * 256 + threadIdx.x;
        if (idx >= (long long)NN * 512) return;
        int n = (int)(idx >> 9);
        int col = (int)(idx & 511);
        int grp = col >> 7;
        int c = col & 127;
        const float* W; const float* b;
        if      (grp == 0) { W = Wq; b = bq; }
        else if (grp == 1) { W = Wk; b = bk; }
        else if (grp == 2) { W = Wv; b = bv; }
        else               { W = Ws; b = bs; }
        float x0 = x[n * 4 + 0], x1 = x[n * 4 + 1], x2 = x[n * 4 + 2], x3 = x[n * 4 + 3];
        float v = b[c] + x0 * W[c] + x1 * W[128 + c] + x2 * W[256 + c] + x3 * W[384 + c];
        if      (grp == 0) g_q[(size_t)n * CC + c] = v;
        else if (grp == 1) g_kvh[(size_t)n * 256 + c] = __float2half_rn(v);
        else if (grp == 2) g_kvh[(size_t)n * 256 + 128 + c] = __float2half_rn(v);
        else               g_s[(size_t)n * CC + c] = v;
    }
}

// ---------------- main projection GEMM: [NN,128] @ [128,128] x4 groups ----------------
// 128x128 tile, 512 threads, 8x4 microtile, BK=16, f32x2 FMA, DOUBLE-BUFFERED smem
#define AS_STRIDE 132
__global__ __launch_bounds__(512) void k_gemm(int inSel,
                        const float* __restrict__ Wq, const float* __restrict__ bq,
                        const float* __restrict__ Wk, const float* __restrict__ bk,
                        const float* __restrict__ Wv, const float* __restrict__ bv,
                        const float* __restrict__ Ws, const float* __restrict__ bs) {
    const float* __restrict__ H = inSel ? g_hB : g_hA;
    __shared__ __align__(16) float As[2][16 * AS_STRIDE];
    __shared__ __align__(16) float Bs[2][16 * 128];

    int tid = threadIdx.x;
    int tx = tid & 31;          // 32 col groups of 4
    int ty = tid >> 5;          // 16 row groups of 8 (warp-uniform)
    int row0 = blockIdx.y * 128;
    int grp = blockIdx.x;       // 0..3 : q,k,v,s
    const float* W; const float* b;
    if      (grp == 0) { W = Wq; b = bq; }
    else if (grp == 1) { W = Wk; b = bk; }
    else if (grp == 2) { W = Wv; b = bv; }
    else               { W = Ws; b = bs; }

    unsigned long long acc[4][4];
#pragma unroll
    for (int i = 0; i < 4; i++)
#pragma unroll
        for (int j = 0; j < 4; j++) acc[i][j] = 0ULL;

    int am = tid >> 2;            // 0..127 row within tile
    int ak = (tid & 3) * 4;       // k offset (float4)
    int bkL = tid >> 5;           // 0..15
    int bnL = (tid & 31) * 4;     // 0..124
    bool arow_ok = (row0 + am < NN);
    const float* Aptr = &H[(size_t)(row0 + am) * 128 + ak];

    // prologue: load tile 0
    float4 pa = arow_ok ? *(const float4*)Aptr : make_float4(0.f, 0.f, 0.f, 0.f);
    float4 pb = *(const float4*)&W[(size_t)bkL * 128 + bnL];
    As[0][(ak + 0) * AS_STRIDE + am] = pa.x;
    As[0][(ak + 1) * AS_STRIDE + am] = pa.y;
    As[0][(ak + 2) * AS_STRIDE + am] = pa.z;
    As[0][(ak + 3) * AS_STRIDE + am] = pa.w;
    *(float4*)&Bs[0][bkL * 128 + bnL] = pb;
    __syncthreads();

    int cur = 0;
    for (int kk = 0; kk < 128; kk += 16) {
        int nxt = kk + 16;
        if (nxt < 128) {   // prefetch next tile (LDG issued before compute)
            pa = arow_ok ? *(const float4*)(Aptr + nxt) : make_float4(0.f, 0.f, 0.f, 0.f);
            pb = *(const float4*)&W[(size_t)(nxt + bkL) * 128 + bnL];
        }
#pragma unroll
        for (int k = 0; k < 16; k++) {
            ulonglong2 a01 = *(const ulonglong2*)&As[cur][k * AS_STRIDE + ty * 8];
            ulonglong2 a23 = *(const ulonglong2*)&As[cur][k * AS_STRIDE + ty * 8 + 4];
            float4 b4 = *(const float4*)&Bs[cur][k * 128 + tx * 4];
            unsigned long long ap[4] = {a01.x, a01.y, a23.x, a23.y};
            unsigned long long br[4] = {rep2(b4.x), rep2(b4.y), rep2(b4.z), rep2(b4.w)};
#pragma unroll
            for (int ip = 0; ip < 4; ip++)
#pragma unroll
                for (int j = 0; j < 4; j++) FFMA_X2(acc[ip][j], ap[ip], br[j]);
        }
        if (nxt < 128) {
            int nb = cur ^ 1;
            As[nb][(ak + 0) * AS_STRIDE + am] = pa.x;
            As[nb][(ak + 1) * AS_STRIDE + am] = pa.y;
            As[nb][(ak + 2) * AS_STRIDE + am] = pa.z;
            As[nb][(ak + 3) * AS_STRIDE + am] = pa.w;
            *(float4*)&Bs[nb][bkL * 128 + bnL] = pb;
        }
        __syncthreads();
        cur ^= 1;
    }

    float4 bias = *(const float4*)&b[tx * 4];
    float bb[4] = {bias.x, bias.y, bias.z, bias.w};
#pragma unroll
    for (int ip = 0; ip < 4; ip++) {
        U64F2 c0, c1, c2, c3;
        c0.u = acc[ip][0]; c1.u = acc[ip][1]; c2.u = acc[ip][2]; c3.u = acc[ip][3];
#pragma unroll
        for (int half = 0; half < 2; half++) {
            int r = row0 + ty * 8 + 2 * ip + half;
            if (r >= NN) continue;
            float4 o;
            if (half == 0) {
                o.x = c0.f.x + bb[0]; o.y = c1.f.x + bb[1];
                o.z = c2.f.x + bb[2]; o.w = c3.f.x + bb[3];
            } else {
                o.x = c0.f.y + bb[0]; o.y = c1.f.y + bb[1];
                o.z = c2.f.y + bb[2]; o.w = c3.f.y + bb[3];
            }
            if (grp == 0) {
                *(float4*)&g_q[(size_t)r * CC + tx * 4] = o;
            } else if (grp == 3) {
                *(float4*)&g_s[(size_t)r * CC + tx * 4] = o;
            } else {
                __half2 h0 = __floats2half2_rn(o.x, o.y);
                __half2 h1 = __floats2half2_rn(o.z, o.w);
                uint2 u;
                u.x = *(unsigned int*)&h0;
                u.y = *(unsigned int*)&h1;
                size_t off = (size_t)r * 256 + (grp == 2 ? 128 : 0) + tx * 4;
                *(uint2*)&g_kvh[off] = u;
            }
        }
    }
}

// ---------------- edge aggregation: warp per dst node, online softmax ----------------
__device__ __forceinline__ float4 ld_kv4(const __half* base, int idx) {
    uint2 u = *(const uint2*)(base + idx);
    __half2 h0 = *(__half2*)&u.x;
    __half2 h1 = *(__half2*)&u.y;
    float2 f0 = __half22float2(h0);
    float2 f1 = __half22float2(h1);
    return make_float4(f0.x, f0.y, f1.x, f1.y);
}

__global__ __launch_bounds__(256) void k_agg(const float* __restrict__ We,
                                             int outSel) {
    __shared__ float sWe[384];
    for (int i = threadIdx.x; i < 384; i += 256) sWe[i] = We[i];
    __syncthreads();

    int node = blockIdx.x * 8 + (threadIdx.x >> 5);
    if (node >= NN) return;
    int lane = threadIdx.x & 31;

    float4 qv = *(const float4*)&g_q[(size_t)node * CC + lane * 4];

    float t0, t1, t2;
    {
        int c = lane * 4;
        t0 = sWe[c] * qv.x + sWe[c + 1] * qv.y + sWe[c + 2] * qv.z + sWe[c + 3] * qv.w;
        c += 128;
        t1 = sWe[c] * qv.x + sWe[c + 1] * qv.y + sWe[c + 2] * qv.z + sWe[c + 3] * qv.w;
        c += 128;
        t2 = sWe[c] * qv.x + sWe[c + 1] * qv.y + sWe[c + 2] * qv.z + sWe[c + 3] * qv.w;
#pragma unroll
        for (int o = 16; o > 0; o >>= 1) {
            t0 += __shfl_xor_sync(0xffffffffu, t0, o);
            t1 += __shfl_xor_sync(0xffffffffu, t1, o);
            t2 += __shfl_xor_sync(0xffffffffu, t2, o);
        }
    }

    float m = -CUDART_INF_F, den = 0.f;
    float4 acc = make_float4(0.f, 0.f, 0.f, 0.f);
    float s0 = 0.f, s1 = 0.f, s2 = 0.f;
    const float scale = 0.08838834764831845f;

    int beg = __ldg(&g_off[node]), end = __ldg(&g_off[node + 1]);
    int p = beg;
    for (; p + 2 <= end; p += 2) {
        int n0 = __ldg(&g_srcA[p]), n1 = __ldg(&g_srcA[p + 1]);
        float4 ea0 = g_eaC[p], ea1 = g_eaC[p + 1];
        const __half* b0 = &g_kvh[(size_t)n0 * 256];
        const __half* b1 = &g_kvh[(size_t)n1 * 256];
        float4 kv0 = ld_kv4(b0, lane * 4);
        float4 vv0 = ld_kv4(b0, 128 + lane * 4);
        float4 kv1 = ld_kv4(b1, lane * 4);
        float4 vv1 = ld_kv4(b1, 128 + lane * 4);
        float d0 = qv.x * kv0.x + qv.y * kv0.y + qv.z * kv0.z + qv.w * kv0.w;
        float d1 = qv.x * kv1.x + qv.y * kv1.y + qv.z * kv1.z + qv.w * kv1.w;
#pragma unroll
        for (int o = 16; o > 0; o >>= 1) {
            d0 += __shfl_xor_sync(0xffffffffu, d0, o);
            d1 += __shfl_xor_sync(0xffffffffu, d1, o);
        }
        float l0 = (d0 + ea0.x * t0 + ea0.y * t1 + ea0.z * t2) * scale;
        float l1 = (d1 + ea1.x * t0 + ea1.y * t1 + ea1.z * t2) * scale;
        float nm = fmaxf(m, fmaxf(l0, l1));
        float corr = __expf(m - nm);
        float w0 = __expf(l0 - nm);
        float w1 = __expf(l1 - nm);
        den = den * corr + w0 + w1;
        acc.x = acc.x * corr + w0 * vv0.x + w1 * vv1.x;
        acc.y = acc.y * corr + w0 * vv0.y + w1 * vv1.y;
        acc.z = acc.z * corr + w0 * vv0.z + w1 * vv1.z;
        acc.w = acc.w * corr + w0 * vv0.w + w1 * vv1.w;
        s0 = s0 * corr + w0 * ea0.x + w1 * ea1.x;
        s1 = s1 * corr + w0 * ea0.y + w1 * ea1.y;
        s2 = s2 * corr + w0 * ea0.z + w1 * ea1.z;
        m = nm;
    }
    if (p < end) {
        int n0 = __ldg(&g_srcA[p]);
        float4 ea0 = g_eaC[p];
        const __half* b0 = &g_kvh[(size_t)n0 * 256];
        float4 kv0 = ld_kv4(b0, lane * 4);
        float4 vv0 = ld_kv4(b0, 128 + lane * 4);
        float d0 = qv.x * kv0.x + qv.y * kv0.y + qv.z * kv0.z + qv.w * kv0.w;
#pragma unroll
        for (int o = 16; o > 0; o >>= 1) d0 += __shfl_xor_sync(0xffffffffu, d0, o);
        float l0 = (d0 + ea0.x * t0 + ea0.y * t1 + ea0.z * t2) * scale;
        float nm = fmaxf(m, l0);
        float corr = __expf(m - nm);
        float w0 = __expf(l0 - nm);
        den = den * corr + w0;
        acc.x = acc.x * corr + w0 * vv0.x;
        acc.y = acc.y * corr + w0 * vv0.y;
        acc.z = acc.z * corr + w0 * vv0.z;
        acc.w = acc.w * corr + w0 * vv0.w;
        s0 = s0 * corr + w0 * ea0.x;
        s1 = s1 * corr + w0 * ea0.y;
        s2 = s2 * corr + w0 * ea0.z;
        m = nm;
    }

    float inv = den > 0.f ? 1.f / den : 0.f;
    s0 *= inv; s1 *= inv; s2 *= inv;
    float4 skip = *(const float4*)&g_s[(size_t)node * CC + lane * 4];
    int c = lane * 4;
    float4 o;
    o.x = acc.x * inv + s0 * sWe[c + 0] + s1 * sWe[128 + c + 0] + s2 * sWe[256 + c + 0] + skip.x;
    o.y = acc.y * inv + s0 * sWe[c + 1] + s1 * sWe[128 + c + 1] + s2 * sWe[256 + c + 1] + skip.y;
    o.z = acc.z * inv + s0 * sWe[c + 2] + s1 * sWe[128 + c + 2] + s2 * sWe[256 + c + 2] + skip.z;
    o.w = acc.w * inv + s0 * sWe[c + 3] + s1 * sWe[128 + c + 3] + s2 * sWe[256 + c + 3] + skip.w;
    o.x = o.x > 0.f ? o.x : 0.01f * o.x;
    o.y = o.y > 0.f ? o.y : 0.01f * o.y;
    o.z = o.z > 0.f ? o.z : 0.01f * o.z;
    o.w = o.w > 0.f ? o.w : 0.01f * o.w;
    float* __restrict__ out = outSel ? g_hB : g_hA;
    *(float4*)&out[(size_t)node * CC + c] = o;
}

// ---------------- pooling ----------------
__global__ void k_pool(int hSel) {
    int g = blockIdx.x;
    int c = threadIdx.x;
    const float* h = hSel ? g_hB : g_hA;
    int s = g_gstart[g], e = g_gstart[g + 1];
    float acc = 0.f;
    for (int n = s; n < e; n++) acc += h[(size_t)n * CC + c];
    g_pool[g * CC + c] = acc;
}

// ---------------- MLP head ----------------
__global__ void k_mlp1(const float* __restrict__ W, const float* __restrict__ b) {
    int idx = blockIdx.x * blockDim.x + threadIdx.x;
    if (idx >= GG * L0) return;
    int r = idx >> 9, c = idx & (L0 - 1);
    float s = b[c];
    for (int k = 0; k < CC; k++) s += g_pool[r * CC + k] * W[k * L0 + c];
    g_m1[idx] = s > 0.f ? s : 0.f;
}

__global__ void k_mlp2(const float* __restrict__ W, const float* __restrict__ b) {
    int idx = blockIdx.x * blockDim.x + threadIdx.x;
    if (idx >= GG * L1) return;
    int r = idx >> 8, c = idx & (L1 - 1);
    float s = b[c];
    for (int k = 0; k < L0; k++) s += g_m1[r * L0 + k] * W[k * L1 + c];
    g_m2[idx] = s > 0.f ? s : 0.f;
}

__global__ void k_mlp3(const float* __restrict__ W, const float* __restrict__ b,
                       float* __restrict__ out) {
    int idx = threadIdx.x;
    if (idx >= GG * 2) return;
    int r = idx >> 1, c = idx & 1;
    float s = b[c];
    for (int k = 0; k < L1; k++) s += g_m2[r * L1 + k] * W[k * 2 + c];
    out[idx] = s;
}

// ---------------- launch ----------------
extern "C" void kernel_launch(void* const* d_in, const int* in_sizes, int n_in,
                              void* d_out, int out_size) {
    const float* x     = (const float*)d_in[0];
    const int*   ei    = (const int*)d_in[1];
    const float* ea    = (const float*)d_in[2];
    const int*   batch = (const int*)d_in[3];
    const float* Wq0 = (const float*)d_in[4];  const float* bq0 = (const float*)d_in[5];
    const float* Wk0 = (const float*)d_in[6];  const float* bk0 = (const float*)d_in[7];
    const float* Wv0 = (const float*)d_in[8];  const float* bv0 = (const float*)d_in[9];
    const float* We0 = (const float*)d_in[10];
    const float* Ws0 = (const float*)d_in[11]; const float* bs0 = (const float*)d_in[12];
    const float* Wq1 = (const float*)d_in[13]; const float* bq1 = (const float*)d_in[14];
    const float* Wk1 = (const float*)d_in[15]; const float* bk1 = (const float*)d_in[16];
    const float* Wv1 = (const float*)d_in[17]; const float* bv1 = (const float*)d_in[18];
    const float* We1 = (const float*)d_in[19];
    const float* Ws1 = (const float*)d_in[20]; const float* bs1 = (const float*)d_in[21];
    const float* Wl0 = (const float*)d_in[22]; const float* bl0 = (const float*)d_in[23];
    const float* Wl1 = (const float*)d_in[24]; const float* bl1 = (const float*)d_in[25];
    const float* Wl2 = (const float*)d_in[26]; const float* bl2 = (const float*)d_in[27];
    float* out = (float*)d_out;

    // CSR build
    k_zero<<<(NN + 255) / 256, 256>>>();
    k_count<<<(EE + 255) / 256, 256>>>(ei);
    k_sum<<<SCAN_NBLK, SCAN_BLK>>>();
    k_scat<<<SCAN_NBLK, SCAN_BLK>>>(batch);
    k_prep<<<FILL_BLKS + G0_BLKS, 256>>>(ei, ea, x,
                                         Wq0, bq0, Wk0, bk0, Wv0, bv0, Ws0, bs0);

    dim3 gemmGrid(4, (NN + 127) / 128);

    // layer 0
    k_agg<<<(NN + 7) / 8, 256>>>(We0, 0);              // -> hA
    // layer 1 (shared weights)
    k_gemm<<<gemmGrid, 512>>>(0, Wq1, bq1, Wk1, bk1, Wv1, bv1, Ws1, bs1);
    k_agg<<<(NN + 7) / 8, 256>>>(We1, 1);              // -> hB
    // layer 2 (same weights)
    k_gemm<<<gemmGrid, 512>>>(1, Wq1, bq1, Wk1, bk1, Wv1, bv1, Ws1, bs1);
    k_agg<<<(NN + 7) / 8, 256>>>(We1, 0);              // -> hA

    // global add pool
    k_pool<<<GG, CC>>>(0);

    // MLP head
    k_mlp1<<<(GG * L0 + 255) / 256, 256>>>(Wl0, bl0);
    k_mlp2<<<(GG * L1 + 255) / 256, 256>>>(Wl1, bl1);
    k_mlp3<<<1, 256>>>(Wl2, bl2, out);
}

// round 14
// speedup vs baseline: 1.4019x; 1.3795x over previous
#include <cuda_runtime.h>
#include <cuda_fp16.h>
#include <cuda_bf16.h>
#include <math_constants.h>
#include <cstdint>

#define NN 50000
#define EE 800000
#define CC 128
#define GG 128
#define L0 512
#define L1 256

#define N4 (NN / 4)
#define SCAN_BLK 256
#define SCAN_NBLK ((N4 + SCAN_BLK - 1) / SCAN_BLK)   // 49
#define FILL_BLKS ((EE + 255) / 256)                 // 3125
#define G0_BLKS   ((NN * 512) / 256)                 // 100000
#define WT_BLKS   (65536 / 256)                      // 256

// ---------------- scratch ----------------
// g_cnt: zero at static init; k_scat re-zeroes after consuming -> every replay sees zeros.
__device__ float          g_q[(size_t)NN * CC];
__device__ float          g_s[(size_t)NN * CC];
__device__ __half         g_kvh[(size_t)NN * 256];   // k|v fp16
__device__ float          g_hA[(size_t)NN * CC];
__device__ float          g_hB[(size_t)NN * CC];
__device__ __nv_bfloat16  g_h16A[(size_t)NN * CC];   // h bf16 (GEMM A input)
__device__ __nv_bfloat16  g_h16B[(size_t)NN * CC];
__device__ __nv_bfloat16  g_wt16[512 * 128];         // W^T bf16: [n=512][k=128]
__device__ int    g_cnt[NN];
__device__ int    g_off[NN + 4];
__device__ int    g_cur[NN + 4];
__device__ int    g_bsum[SCAN_NBLK];
__device__ int    g_srcA[EE];
__device__ float4 g_eaC[EE];
__device__ int    g_gstart[GG + 1];
__device__ float  g_pool[GG * CC];
__device__ float  g_m1[GG * L0];
__device__ float  g_m2[GG * L1];

__device__ __forceinline__ uint32_t smem_u32(const void* p) {
    uint32_t a;
    asm("{ .reg .u64 t; cvta.to.shared.u64 t, %1; cvt.u32.u64 %0, t; }" : "=r"(a) : "l"(p));
    return a;
}

// ---------------- CSR build ----------------
__global__ void k_count(const int* __restrict__ ei) {
    int e = blockIdx.x * blockDim.x + threadIdx.x;
    if (e < EE) atomicAdd(&g_cnt[ei[EE + e]], 1);
}
__global__ void k_sum() {
    __shared__ int sh[SCAN_BLK];
    int t = threadIdx.x;
    int i4 = blockIdx.x * SCAN_BLK + t;
    int s = 0;
    if (i4 < N4) {
        int4 c = *(const int4*)&g_cnt[i4 * 4];
        s = c.x + c.y + c.z + c.w;
    }
    sh[t] = s;
    __syncthreads();
    for (int d = SCAN_BLK / 2; d > 0; d >>= 1) {
        if (t < d) sh[t] += sh[t + d];
        __syncthreads();
    }
    if (t == 0) g_bsum[blockIdx.x] = sh[0];
}
// scat: inlined block-sum scan, writes off/cur, zeroes g_cnt (for next replay), gstart
__global__ void k_scat(const int* __restrict__ batch) {
    __shared__ int sh[SCAN_BLK];
    __shared__ int bpre[SCAN_NBLK + 1];
    int t = threadIdx.x;
    if (t < SCAN_NBLK) bpre[t] = g_bsum[t];
    __syncthreads();
    if (t == 0) {
        int run = 0;
        for (int i = 0; i < SCAN_NBLK; i++) { int v = bpre[i]; bpre[i] = run; run += v; }
        bpre[SCAN_NBLK] = run;
    }
    __syncthreads();
    int i4 = blockIdx.x * SCAN_BLK + t;
    int4 c = make_int4(0, 0, 0, 0);
    if (i4 < N4) c = *(const int4*)&g_cnt[i4 * 4];
    int s = c.x + c.y + c.z + c.w;
    sh[t] = s;
    __syncthreads();
    for (int d = 1; d < SCAN_BLK; d <<= 1) {
        int u = (t >= d) ? sh[t - d] : 0;
        __syncthreads();
        sh[t] += u;
        __syncthreads();
    }
    if (i4 < N4) {
        int base = bpre[blockIdx.x] + sh[t] - s;
        int4 o;
        o.x = base; o.y = base + c.x; o.z = o.y + c.y; o.w = o.z + c.z;
        *(int4*)&g_off[i4 * 4] = o;
        *(int4*)&g_cur[i4 * 4] = o;
        *(int4*)&g_cnt[i4 * 4] = make_int4(0, 0, 0, 0);   // self-clean
    }
    if (blockIdx.x == 0) {
        if (t == 0) g_off[NN] = bpre[SCAN_NBLK];
        if (t <= GG) {
            int lo = 0, hi = NN;
            while (lo < hi) {
                int mid = (lo + hi) >> 1;
                if (batch[mid] < t) lo = mid + 1; else hi = mid;
            }
            g_gstart[t] = lo;
        }
    }
}

// ---------------- fused: CSR fill + layer-0 projection + W transpose (bf16) ----------------
__global__ void k_prep(const int* __restrict__ ei, const float* __restrict__ ea,
                       const float* __restrict__ x,
                       const float* __restrict__ Wq, const float* __restrict__ bq,
                       const float* __restrict__ Wk, const float* __restrict__ bk,
                       const float* __restrict__ Wv, const float* __restrict__ bv,
                       const float* __restrict__ Ws, const float* __restrict__ bs,
                       const float* __restrict__ Wq1, const float* __restrict__ Wk1,
                       const float* __restrict__ Wv1, const float* __restrict__ Ws1) {
    if (blockIdx.x < FILL_BLKS) {
        int e = blockIdx.x * 256 + threadIdx.x;
        if (e < EE) {
            int d = ei[EE + e];
            int p = atomicAdd(&g_cur[d], 1);
            g_srcA[p] = ei[e];
            float4 v;
            v.x = ea[e * 3 + 0]; v.y = ea[e * 3 + 1]; v.z = ea[e * 3 + 2]; v.w = 0.f;
            g_eaC[p] = v;
        }
    } else if (blockIdx.x < FILL_BLKS + G0_BLKS) {
        long long idx = (long long)(blockIdx.x - FILL_BLKS) * 256 + threadIdx.x;
        if (idx >= (long long)NN * 512) return;
        int n = (int)(idx >> 9);
        int col = (int)(idx & 511);
        int grp = col >> 7;
        int c = col & 127;
        const float* W; const float* b;
        if      (grp == 0) { W = Wq; b = bq; }
        else if (grp == 1) { W = Wk; b = bk; }
        else if (grp == 2) { W = Wv; b = bv; }
        else               { W = Ws; b = bs; }
        float x0 = x[n * 4 + 0], x1 = x[n * 4 + 1], x2 = x[n * 4 + 2], x3 = x[n * 4 + 3];
        float v = b[c] + x0 * W[c] + x1 * W[128 + c] + x2 * W[256 + c] + x3 * W[384 + c];
        if      (grp == 0) g_q[(size_t)n * CC + c] = v;
        else if (grp == 1) g_kvh[(size_t)n * 256 + c] = __float2half_rn(v);
        else if (grp == 2) g_kvh[(size_t)n * 256 + 128 + c] = __float2half_rn(v);
        else               g_s[(size_t)n * CC + c] = v;
    } else {
        int ii = (blockIdx.x - FILL_BLKS - G0_BLKS) * 256 + threadIdx.x;
        if (ii >= 65536) return;
        int n = ii >> 7;        // 0..511 output channel
        int k = ii & 127;
        int grp = n >> 7, nl = n & 127;
        const float* W;
        if      (grp == 0) W = Wq1;
        else if (grp == 1) W = Wk1;
        else if (grp == 2) W = Wv1;
        else               W = Ws1;
        g_wt16[ii] = __float2bfloat16(W[k * 128 + nl]);
    }
}

// ---------------- HMMA projection GEMM (mma.sync bf16, sm_80+ baseline PTX) ----------------
// out[nodes, 512] = h[nodes, 128] @ W[128, 512]; A bf16 row-major, B = W^T [n][k] col-major.
#define HG_A 0
#define HG_B 32768
#define HG_BIAS 65536
#define HG_SMEM 66048

// smem layout: row-major 256B/row, 16B chunks XOR-swizzled by row for conflict-free ldmatrix
__device__ __forceinline__ uint32_t sw_off(int row, int cb) {
    return (uint32_t)row * 256 + (uint32_t)(((cb ^ (row & 7)) & 15) << 4);
}

__global__ __launch_bounds__(256) void k_hgemm(int inSel,
        const float* __restrict__ bq, const float* __restrict__ bk2,
        const float* __restrict__ bv, const float* __restrict__ bs) {
    extern __shared__ char smem[];
    uint32_t sb = smem_u32(smem);
    int tid = threadIdx.x;
    int wid = tid >> 5;
    int lane = tid & 31;
    int grp = blockIdx.x;             // 0..3 : q,k,v,s
    int row0 = blockIdx.y * 128;
    const __nv_bfloat16* __restrict__ Hbf = inSel ? g_h16B : g_h16A;
    float* sBias = (float*)(smem + HG_BIAS);

    // A tile: 128 rows x 128 k bf16 (256B/row)
    for (int i = tid; i < 2048; i += 256) {
        int row = i >> 4, cb = i & 15;
        uint4 v = make_uint4(0u, 0u, 0u, 0u);
        int gr = row0 + row;
        if (gr < NN) v = *(const uint4*)&Hbf[(size_t)gr * 128 + cb * 8];
        *(uint4*)(smem + HG_A + sw_off(row, cb)) = v;
    }
    // B tile: 128 n x 128 k bf16 (this col-group)
    for (int i = tid; i < 2048; i += 256) {
        int nl = i >> 4, cb = i & 15;
        uint4 v = *(const uint4*)&g_wt16[(size_t)(grp * 128 + nl) * 128 + cb * 8];
        *(uint4*)(smem + HG_B + sw_off(nl, cb)) = v;
    }
    if (tid < 128) {
        const float* b = (grp == 0) ? bq : (grp == 1) ? bk2 : (grp == 2) ? bv : bs;
        sBias[tid] = b[tid];
    }
    __syncthreads();

    float acc[16][4];
#pragma unroll
    for (int j = 0; j < 16; j++)
#pragma unroll
        for (int q = 0; q < 4; q++) acc[j][q] = 0.f;

    int warpRow = wid * 16;
    int arow = warpRow + (lane & 15);
    int akc = lane >> 4;                          // 0/1: k-half
    int bn = (lane & 7) + ((lane >> 4) << 3);     // n within 16-wide pair
    int bkc = (lane >> 3) & 1;                    // k-half

#pragma unroll
    for (int ks = 0; ks < 8; ks++) {
        uint32_t a0, a1, a2, a3;
        uint32_t aaddr = sb + HG_A + sw_off(arow, ks * 2 + akc);
        asm volatile("ldmatrix.sync.aligned.m8n8.x4.shared.b16 {%0,%1,%2,%3}, [%4];"
                     : "=r"(a0), "=r"(a1), "=r"(a2), "=r"(a3) : "r"(aaddr));
#pragma unroll
        for (int jp = 0; jp < 8; jp++) {
            uint32_t b0, b1, b2, b3;
            uint32_t baddr = sb + HG_B + sw_off(jp * 16 + bn, ks * 2 + bkc);
            asm volatile("ldmatrix.sync.aligned.m8n8.x4.shared.b16 {%0,%1,%2,%3}, [%4];"
                         : "=r"(b0), "=r"(b1), "=r"(b2), "=r"(b3) : "r"(baddr));
            asm volatile(
                "mma.sync.aligned.m16n8k16.row.col.f32.bf16.bf16.f32 "
                "{%0,%1,%2,%3}, {%4,%5,%6,%7}, {%8,%9}, {%0,%1,%2,%3};"
                : "+f"(acc[2 * jp][0]), "+f"(acc[2 * jp][1]),
                  "+f"(acc[2 * jp][2]), "+f"(acc[2 * jp][3])
                : "r"(a0), "r"(a1), "r"(a2), "r"(a3), "r"(b0), "r"(b1));
            asm volatile(
                "mma.sync.aligned.m16n8k16.row.col.f32.bf16.bf16.f32 "
                "{%0,%1,%2,%3}, {%4,%5,%6,%7}, {%8,%9}, {%0,%1,%2,%3};"
                : "+f"(acc[2 * jp + 1][0]), "+f"(acc[2 * jp + 1][1]),
                  "+f"(acc[2 * jp + 1][2]), "+f"(acc[2 * jp + 1][3])
                : "r"(a0), "r"(a1), "r"(a2), "r"(a3), "r"(b2), "r"(b3));
        }
    }

    // epilogue: c0,c1 -> row g, cols tq*2..+1; c2,c3 -> row g+8
    int g = lane >> 2, tq = lane & 3;
    int rA = row0 + warpRow + g;
    int rB = rA + 8;
    bool okA = rA < NN, okB = rB < NN;
#pragma unroll
    for (int j = 0; j < 16; j++) {
        int c = j * 8 + tq * 2;
        float bx = sBias[c], by = sBias[c + 1];
        float2 vA = make_float2(acc[j][0] + bx, acc[j][1] + by);
        float2 vB = make_float2(acc[j][2] + bx, acc[j][3] + by);
        if (grp == 0) {
            if (okA) *(float2*)&g_q[(size_t)rA * CC + c] = vA;
            if (okB) *(float2*)&g_q[(size_t)rB * CC + c] = vB;
        } else if (grp == 3) {
            if (okA) *(float2*)&g_s[(size_t)rA * CC + c] = vA;
            if (okB) *(float2*)&g_s[(size_t)rB * CC + c] = vB;
        } else {
            int off = (grp == 2) ? 128 : 0;
            if (okA) { __half2 h = __floats2half2_rn(vA.x, vA.y); *(__half2*)&g_kvh[(size_t)rA * 256 + off + c] = h; }
            if (okB) { __half2 h = __floats2half2_rn(vB.x, vB.y); *(__half2*)&g_kvh[(size_t)rB * 256 + off + c] = h; }
        }
    }
}

// ---------------- edge aggregation ----------------
__device__ __forceinline__ float4 ld_kv4(const __half* base, int idx) {
    uint2 u = *(const uint2*)(base + idx);
    __half2 h0 = *(__half2*)&u.x;
    __half2 h1 = *(__half2*)&u.y;
    float2 f0 = __half22float2(h0);
    float2 f1 = __half22float2(h1);
    return make_float4(f0.x, f0.y, f1.x, f1.y);
}

__global__ __launch_bounds__(256) void k_agg(const float* __restrict__ We,
                                             int outSel) {
    __shared__ float sWe[384];
    for (int i = threadIdx.x; i < 384; i += 256) sWe[i] = We[i];
    __syncthreads();

    int node = blockIdx.x * 8 + (threadIdx.x >> 5);
    if (node >= NN) return;
    int lane = threadIdx.x & 31;

    float4 qv = *(const float4*)&g_q[(size_t)node * CC + lane * 4];

    float t0, t1, t2;
    {
        int c = lane * 4;
        t0 = sWe[c] * qv.x + sWe[c + 1] * qv.y + sWe[c + 2] * qv.z + sWe[c + 3] * qv.w;
        c += 128;
        t1 = sWe[c] * qv.x + sWe[c + 1] * qv.y + sWe[c + 2] * qv.z + sWe[c + 3] * qv.w;
        c += 128;
        t2 = sWe[c] * qv.x + sWe[c + 1] * qv.y + sWe[c + 2] * qv.z + sWe[c + 3] * qv.w;
#pragma unroll
        for (int o = 16; o > 0; o >>= 1) {
            t0 += __shfl_xor_sync(0xffffffffu, t0, o);
            t1 += __shfl_xor_sync(0xffffffffu, t1, o);
            t2 += __shfl_xor_sync(0xffffffffu, t2, o);
        }
    }

    float m = -CUDART_INF_F, den = 0.f;
    float4 acc = make_float4(0.f, 0.f, 0.f, 0.f);
    float s0 = 0.f, s1 = 0.f, s2 = 0.f;
    const float scale = 0.08838834764831845f;

    int beg = __ldg(&g_off[node]), end = __ldg(&g_off[node + 1]);
    int p = beg;
    for (; p + 2 <= end; p += 2) {
        int n0 = __ldg(&g_srcA[p]), n1 = __ldg(&g_srcA[p + 1]);
        float4 ea0 = g_eaC[p], ea1 = g_eaC[p + 1];
        const __half* b0 = &g_kvh[(size_t)n0 * 256];
        const __half* b1 = &g_kvh[(size_t)n1 * 256];
        float4 kv0 = ld_kv4(b0, lane * 4);
        float4 vv0 = ld_kv4(b0, 128 + lane * 4);
        float4 kv1 = ld_kv4(b1, lane * 4);
        float4 vv1 = ld_kv4(b1, 128 + lane * 4);
        float d0 = qv.x * kv0.x + qv.y * kv0.y + qv.z * kv0.z + qv.w * kv0.w;
        float d1 = qv.x * kv1.x + qv.y * kv1.y + qv.z * kv1.z + qv.w * kv1.w;
#pragma unroll
        for (int o = 16; o > 0; o >>= 1) {
            d0 += __shfl_xor_sync(0xffffffffu, d0, o);
            d1 += __shfl_xor_sync(0xffffffffu, d1, o);
        }
        float l0 = (d0 + ea0.x * t0 + ea0.y * t1 + ea0.z * t2) * scale;
        float l1 = (d1 + ea1.x * t0 + ea1.y * t1 + ea1.z * t2) * scale;
        float nm = fmaxf(m, fmaxf(l0, l1));
        float corr = __expf(m - nm);
        float w0 = __expf(l0 - nm);
        float w1 = __expf(l1 - nm);
        den = den * corr + w0 + w1;
        acc.x = acc.x * corr + w0 * vv0.x + w1 * vv1.x;
        acc.y = acc.y * corr + w0 * vv0.y + w1 * vv1.y;
        acc.z = acc.z * corr + w0 * vv0.z + w1 * vv1.z;
        acc.w = acc.w * corr + w0 * vv0.w + w1 * vv1.w;
        s0 = s0 * corr + w0 * ea0.x + w1 * ea1.x;
        s1 = s1 * corr + w0 * ea0.y + w1 * ea1.y;
        s2 = s2 * corr + w0 * ea0.z + w1 * ea1.z;
        m = nm;
    }
    if (p < end) {
        int n0 = __ldg(&g_srcA[p]);
        float4 ea0 = g_eaC[p];
        const __half* b0 = &g_kvh[(size_t)n0 * 256];
        float4 kv0 = ld_kv4(b0, lane * 4);
        float4 vv0 = ld_kv4(b0, 128 + lane * 4);
        float d0 = qv.x * kv0.x + qv.y * kv0.y + qv.z * kv0.z + qv.w * kv0.w;
#pragma unroll
        for (int o = 16; o > 0; o >>= 1) d0 += __shfl_xor_sync(0xffffffffu, d0, o);
        float l0 = (d0 + ea0.x * t0 + ea0.y * t1 + ea0.z * t2) * scale;
        float nm = fmaxf(m, l0);
        float corr = __expf(m - nm);
        float w0 = __expf(l0 - nm);
        den = den * corr + w0;
        acc.x = acc.x * corr + w0 * vv0.x;
        acc.y = acc.y * corr + w0 * vv0.y;
        acc.z = acc.z * corr + w0 * vv0.z;
        acc.w = acc.w * corr + w0 * vv0.w;
        s0 = s0 * corr + w0 * ea0.x;
        s1 = s1 * corr + w0 * ea0.y;
        s2 = s2 * corr + w0 * ea0.z;
        m = nm;
    }

    float inv = den > 0.f ? 1.f / den : 0.f;
    s0 *= inv; s1 *= inv; s2 *= inv;
    float4 skip = *(const float4*)&g_s[(size_t)node * CC + lane * 4];
    int c = lane * 4;
    float4 o;
    o.x = acc.x * inv + s0 * sWe[c + 0] + s1 * sWe[128 + c + 0] + s2 * sWe[256 + c + 0] + skip.x;
    o.y = acc.y * inv + s0 * sWe[c + 1] + s1 * sWe[128 + c + 1] + s2 * sWe[256 + c + 1] + skip.y;
    o.z = acc.z * inv + s0 * sWe[c + 2] + s1 * sWe[128 + c + 2] + s2 * sWe[256 + c + 2] + skip.z;
    o.w = acc.w * inv + s0 * sWe[c + 3] + s1 * sWe[128 + c + 3] + s2 * sWe[256 + c + 3] + skip.w;
    o.x = o.x > 0.f ? o.x : 0.01f * o.x;
    o.y = o.y > 0.f ? o.y : 0.01f * o.y;
    o.z = o.z > 0.f ? o.z : 0.01f * o.z;
    o.w = o.w > 0.f ? o.w : 0.01f * o.w;
    float* __restrict__ out = outSel ? g_hB : g_hA;
    *(float4*)&out[(size_t)node * CC + c] = o;
    __nv_bfloat16* __restrict__ out16 = outSel ? g_h16B : g_h16A;
    __nv_bfloat162 p0 = __floats2bfloat162_rn(o.x, o.y);
    __nv_bfloat162 p1 = __floats2bfloat162_rn(o.z, o.w);
    uint2 u;
    u.x = *(unsigned int*)&p0;
    u.y = *(unsigned int*)&p1;
    *(uint2*)&out16[(size_t)node * CC + c] = u;
}

// ---------------- pooling ----------------
__global__ void k_pool(int hSel) {
    int g = blockIdx.x;
    int c = threadIdx.x;
    const float* h = hSel ? g_hB : g_hA;
    int s = g_gstart[g], e = g_gstart[g + 1];
    float acc = 0.f;
    for (int n = s; n < e; n++) acc += h[(size_t)n * CC + c];
    g_pool[g * CC + c] = acc;
}

// ---------------- MLP head ----------------
__global__ void k_mlp1(const float* __restrict__ W, const float* __restrict__ b) {
    int idx = blockIdx.x * blockDim.x + threadIdx.x;
    if (idx >= GG * L0) return;
    int r = idx >> 9, c = idx & (L0 - 1);
    float s = b[c];
    for (int k = 0; k < CC; k++) s += g_pool[r * CC + k] * W[k * L0 + c];
    g_m1[idx] = s > 0.f ? s : 0.f;
}
__global__ void k_mlp2(const float* __restrict__ W, const float* __restrict__ b) {
    int idx = blockIdx.x * blockDim.x + threadIdx.x;
    if (idx >= GG * L1) return;
    int r = idx >> 8, c = idx & (L1 - 1);
    float s = b[c];
    for (int k = 0; k < L0; k++) s += g_m1[r * L0 + k] * W[k * L1 + c];
    g_m2[idx] = s > 0.f ? s : 0.f;
}
__global__ void k_mlp3(const float* __restrict__ W, const float* __restrict__ b,
                       float* __restrict__ out) {
    int idx = threadIdx.x;
    if (idx >= GG * 2) return;
    int r = idx >> 1, c = idx & 1;
    float s = b[c];
    for (int k = 0; k < L1; k++) s += g_m2[r * L1 + k] * W[k * 2 + c];
    out[idx] = s;
}

// ---------------- launch ----------------
extern "C" void kernel_launch(void* const* d_in, const int* in_sizes, int n_in,
                              void* d_out, int out_size) {
    const float* x     = (const float*)d_in[0];
    const int*   ei    = (const int*)d_in[1];
    const float* ea    = (const float*)d_in[2];
    const int*   batch = (const int*)d_in[3];
    const float* Wq0 = (const float*)d_in[4];  const float* bq0 = (const float*)d_in[5];
    const float* Wk0 = (const float*)d_in[6];  const float* bk0 = (const float*)d_in[7];
    const float* Wv0 = (const float*)d_in[8];  const float* bv0 = (const float*)d_in[9];
    const float* We0 = (const float*)d_in[10];
    const float* Ws0 = (const float*)d_in[11]; const float* bs0 = (const float*)d_in[12];
    const float* Wq1 = (const float*)d_in[13]; const float* bq1 = (const float*)d_in[14];
    const float* Wk1 = (const float*)d_in[15]; const float* bk1 = (const float*)d_in[16];
    const float* Wv1 = (const float*)d_in[17]; const float* bv1 = (const float*)d_in[18];
    const float* We1 = (const float*)d_in[19];
    const float* Ws1 = (const float*)d_in[20]; const float* bs1 = (const float*)d_in[21];
    const float* Wl0 = (const float*)d_in[22]; const float* bl0 = (const float*)d_in[23];
    const float* Wl1 = (const float*)d_in[24]; const float* bl1 = (const float*)d_in[25];
    const float* Wl2 = (const float*)d_in[26]; const float* bl2 = (const float*)d_in[27];
    float* out = (float*)d_out;

    cudaFuncSetAttribute(k_hgemm, cudaFuncAttributeMaxDynamicSharedMemorySize, HG_SMEM);

    // CSR build (g_cnt starts zero; k_scat self-cleans it each run)
    k_count<<<(EE + 255) / 256, 256>>>(ei);
    k_sum<<<SCAN_NBLK, SCAN_BLK>>>();
    k_scat<<<SCAN_NBLK, SCAN_BLK>>>(batch);
    k_prep<<<FILL_BLKS + G0_BLKS + WT_BLKS, 256>>>(ei, ea, x,
                                                   Wq0, bq0, Wk0, bk0, Wv0, bv0, Ws0, bs0,
                                                   Wq1, Wk1, Wv1, Ws1);

    dim3 hgGrid(4, (NN + 127) / 128);

    // layer 0
    k_agg<<<(NN + 7) / 8, 256>>>(We0, 0);              // -> hA / h16A
    // layer 1 (shared weights)
    k_hgemm<<<hgGrid, 256, HG_SMEM>>>(0, bq1, bk1, bv1, bs1);
    k_agg<<<(NN + 7) / 8, 256>>>(We1, 1);              // -> hB / h16B
    // layer 2 (same weights)
    k_hgemm<<<hgGrid, 256, HG_SMEM>>>(1, bq1, bk1, bv1, bs1);
    k_agg<<<(NN + 7) / 8, 256>>>(We1, 0);              // -> hA

    // pool + MLP head
    k_pool<<<GG, CC>>>(0);
    k_mlp1<<<(GG * L0 + 255) / 256, 256>>>(Wl0, bl0);
    k_mlp2<<<(GG * L1 + 255) / 256, 256>>>(Wl1, bl1);
    k_mlp3<<<1, 256>>>(Wl2, bl2, out);
}

// round 16
// speedup vs baseline: 1.5532x; 1.1080x over previous
#include <cuda_runtime.h>
#include <cuda_fp16.h>
#include <cuda_bf16.h>
#include <math_constants.h>
#include <cstdint>

#define NN 50000
#define EE 800000
#define CC 128
#define GG 128
#define L0 512
#define L1 256

#define N4 (NN / 4)
#define SCAN_BLK 256
#define SCAN_NBLK ((N4 + SCAN_BLK - 1) / SCAN_BLK)   // 49
#define FILL_BLKS ((EE + 255) / 256)                 // 3125
#define G0_BLKS   ((NN * 128) / 256)                 // 25000  (4 cols/thread)
#define WT_BLKS   (65536 / 256)                      // 256

// ---------------- scratch ----------------
// g_cnt: zero at static init; k_scat re-zeroes after consuming -> every replay sees zeros.
__device__ float          g_q[(size_t)NN * CC];
__device__ float          g_s[(size_t)NN * CC];
__device__ __half         g_kvh[(size_t)NN * 256];   // k|v fp16
__device__ float          g_hA[(size_t)NN * CC];     // fp32 h (only final layer writes)
__device__ __nv_bfloat16  g_h16A[(size_t)NN * CC];   // h bf16 (GEMM A input)
__device__ __nv_bfloat16  g_h16B[(size_t)NN * CC];
__device__ __nv_bfloat16  g_wt16[512 * 128];         // W^T bf16: [n=512][k=128]
__device__ int    g_cnt[NN];
__device__ int    g_off[NN + 4];
__device__ int    g_cur[NN + 4];
__device__ int    g_bsum[SCAN_NBLK];
__device__ int    g_srcA[EE];
__device__ float4 g_eaC[EE];
__device__ int    g_gstart[GG + 1];
__device__ float  g_pool[GG * CC];
__device__ float  g_m1[GG * L0];
__device__ float  g_m2[GG * L1];

__device__ __forceinline__ uint32_t smem_u32(const void* p) {
    uint32_t a;
    asm("{ .reg .u64 t; cvta.to.shared.u64 t, %1; cvt.u32.u64 %0, t; }" : "=r"(a) : "l"(p));
    return a;
}

// ---------------- CSR build ----------------
__global__ void k_count(const int* __restrict__ ei) {
    int e = blockIdx.x * blockDim.x + threadIdx.x;
    if (e < EE) atomicAdd(&g_cnt[ei[EE + e]], 1);
}
__global__ void k_sum() {
    __shared__ int sh[SCAN_BLK];
    int t = threadIdx.x;
    int i4 = blockIdx.x * SCAN_BLK + t;
    int s = 0;
    if (i4 < N4) {
        int4 c = *(const int4*)&g_cnt[i4 * 4];
        s = c.x + c.y + c.z + c.w;
    }
    sh[t] = s;
    __syncthreads();
    for (int d = SCAN_BLK / 2; d > 0; d >>= 1) {
        if (t < d) sh[t] += sh[t + d];
        __syncthreads();
    }
    if (t == 0) g_bsum[blockIdx.x] = sh[0];
}
// scat: inlined block-sum scan, writes off/cur, zeroes g_cnt (next replay), gstart
__global__ void k_scat(const int* __restrict__ batch) {
    __shared__ int sh[SCAN_BLK];
    __shared__ int bpre[SCAN_NBLK + 1];
    int t = threadIdx.x;
    if (t < SCAN_NBLK) bpre[t] = g_bsum[t];
    __syncthreads();
    if (t == 0) {
        int run = 0;
        for (int i = 0; i < SCAN_NBLK; i++) { int v = bpre[i]; bpre[i] = run; run += v; }
        bpre[SCAN_NBLK] = run;
    }
    __syncthreads();
    int i4 = blockIdx.x * SCAN_BLK + t;
    int4 c = make_int4(0, 0, 0, 0);
    if (i4 < N4) c = *(const int4*)&g_cnt[i4 * 4];
    int s = c.x + c.y + c.z + c.w;
    sh[t] = s;
    __syncthreads();
    for (int d = 1; d < SCAN_BLK; d <<= 1) {
        int u = (t >= d) ? sh[t - d] : 0;
        __syncthreads();
        sh[t] += u;
        __syncthreads();
    }
    if (i4 < N4) {
        int base = bpre[blockIdx.x] + sh[t] - s;
        int4 o;
        o.x = base; o.y = base + c.x; o.z = o.y + c.y; o.w = o.z + c.z;
        *(int4*)&g_off[i4 * 4] = o;
        *(int4*)&g_cur[i4 * 4] = o;
        *(int4*)&g_cnt[i4 * 4] = make_int4(0, 0, 0, 0);   // self-clean
    }
    if (blockIdx.x == 0) {
        if (t == 0) g_off[NN] = bpre[SCAN_NBLK];
        if (t <= GG) {
            int lo = 0, hi = NN;
            while (lo < hi) {
                int mid = (lo + hi) >> 1;
                if (batch[mid] < t) lo = mid + 1; else hi = mid;
            }
            g_gstart[t] = lo;
        }
    }
}

// ---------------- fused: CSR fill + layer-0 projection (4-wide) + W transpose ----------------
__global__ void k_prep(const int* __restrict__ ei, const float* __restrict__ ea,
                       const float* __restrict__ x,
                       const float* __restrict__ Wq, const float* __restrict__ bq,
                       const float* __restrict__ Wk, const float* __restrict__ bk,
                       const float* __restrict__ Wv, const float* __restrict__ bv,
                       const float* __restrict__ Ws, const float* __restrict__ bs,
                       const float* __restrict__ Wq1, const float* __restrict__ Wk1,
                       const float* __restrict__ Wv1, const float* __restrict__ Ws1) {
    if (blockIdx.x < FILL_BLKS) {
        int e = blockIdx.x * 256 + threadIdx.x;
        if (e < EE) {
            int d = ei[EE + e];
            int p = atomicAdd(&g_cur[d], 1);
            g_srcA[p] = ei[e];
            float4 v;
            v.x = ea[e * 3 + 0]; v.y = ea[e * 3 + 1]; v.z = ea[e * 3 + 2]; v.w = 0.f;
            g_eaC[p] = v;
        }
    } else if (blockIdx.x < FILL_BLKS + G0_BLKS) {
        // layer-0 projection, 4 output cols per thread
        int idx = (blockIdx.x - FILL_BLKS) * 256 + threadIdx.x;   // [0, NN*128)
        int n = idx >> 7;
        int j = idx & 127;
        int grp = j >> 5;
        int c = (j & 31) * 4;
        const float* W; const float* b;
        if      (grp == 0) { W = Wq; b = bq; }
        else if (grp == 1) { W = Wk; b = bk; }
        else if (grp == 2) { W = Wv; b = bv; }
        else               { W = Ws; b = bs; }
        float4 xr = *(const float4*)&x[n * 4];
        float4 w0 = *(const float4*)&W[c];
        float4 w1 = *(const float4*)&W[128 + c];
        float4 w2 = *(const float4*)&W[256 + c];
        float4 w3 = *(const float4*)&W[384 + c];
        float4 bb = *(const float4*)&b[c];
        float4 v;
        v.x = bb.x + xr.x * w0.x + xr.y * w1.x + xr.z * w2.x + xr.w * w3.x;
        v.y = bb.y + xr.x * w0.y + xr.y * w1.y + xr.z * w2.y + xr.w * w3.y;
        v.z = bb.z + xr.x * w0.z + xr.y * w1.z + xr.z * w2.z + xr.w * w3.z;
        v.w = bb.w + xr.x * w0.w + xr.y * w1.w + xr.z * w2.w + xr.w * w3.w;
        if (grp == 0) {
            *(float4*)&g_q[(size_t)n * CC + c] = v;
        } else if (grp == 3) {
            *(float4*)&g_s[(size_t)n * CC + c] = v;
        } else {
            __half2 h0 = __floats2half2_rn(v.x, v.y);
            __half2 h1 = __floats2half2_rn(v.z, v.w);
            uint2 u;
            u.x = *(unsigned int*)&h0;
            u.y = *(unsigned int*)&h1;
            *(uint2*)&g_kvh[(size_t)n * 256 + (grp == 2 ? 128 : 0) + c] = u;
        }
    } else {
        int ii = (blockIdx.x - FILL_BLKS - G0_BLKS) * 256 + threadIdx.x;
        if (ii >= 65536) return;
        int n = ii >> 7;        // 0..511 output channel
        int k = ii & 127;
        int grp = n >> 7, nl = n & 127;
        const float* W;
        if      (grp == 0) W = Wq1;
        else if (grp == 1) W = Wk1;
        else if (grp == 2) W = Wv1;
        else               W = Ws1;
        g_wt16[ii] = __float2bfloat16(W[k * 128 + nl]);
    }
}

// ---------------- HMMA projection GEMM (mma.sync bf16) ----------------
#define HG_A 0
#define HG_B 32768
#define HG_BIAS 65536
#define HG_SMEM 66048

__device__ __forceinline__ uint32_t sw_off(int row, int cb) {
    return (uint32_t)row * 256 + (uint32_t)(((cb ^ (row & 7)) & 15) << 4);
}

__global__ __launch_bounds__(256) void k_hgemm(int inSel,
        const float* __restrict__ bq, const float* __restrict__ bk2,
        const float* __restrict__ bv, const float* __restrict__ bs) {
    extern __shared__ char smem[];
    uint32_t sb = smem_u32(smem);
    int tid = threadIdx.x;
    int wid = tid >> 5;
    int lane = tid & 31;
    int grp = blockIdx.x;             // 0..3 : q,k,v,s
    int row0 = blockIdx.y * 128;
    const __nv_bfloat16* __restrict__ Hbf = inSel ? g_h16B : g_h16A;
    float* sBias = (float*)(smem + HG_BIAS);

    for (int i = tid; i < 2048; i += 256) {
        int row = i >> 4, cb = i & 15;
        uint4 v = make_uint4(0u, 0u, 0u, 0u);
        int gr = row0 + row;
        if (gr < NN) v = *(const uint4*)&Hbf[(size_t)gr * 128 + cb * 8];
        *(uint4*)(smem + HG_A + sw_off(row, cb)) = v;
    }
    for (int i = tid; i < 2048; i += 256) {
        int nl = i >> 4, cb = i & 15;
        uint4 v = *(const uint4*)&g_wt16[(size_t)(grp * 128 + nl) * 128 + cb * 8];
        *(uint4*)(smem + HG_B + sw_off(nl, cb)) = v;
    }
    if (tid < 128) {
        const float* b = (grp == 0) ? bq : (grp == 1) ? bk2 : (grp == 2) ? bv : bs;
        sBias[tid] = b[tid];
    }
    __syncthreads();

    float acc[16][4];
#pragma unroll
    for (int j = 0; j < 16; j++)
#pragma unroll
        for (int q = 0; q < 4; q++) acc[j][q] = 0.f;

    int warpRow = wid * 16;
    int arow = warpRow + (lane & 15);
    int akc = lane >> 4;
    int bn = (lane & 7) + ((lane >> 4) << 3);
    int bkc = (lane >> 3) & 1;

#pragma unroll
    for (int ks = 0; ks < 8; ks++) {
        uint32_t a0, a1, a2, a3;
        uint32_t aaddr = sb + HG_A + sw_off(arow, ks * 2 + akc);
        asm volatile("ldmatrix.sync.aligned.m8n8.x4.shared.b16 {%0,%1,%2,%3}, [%4];"
                     : "=r"(a0), "=r"(a1), "=r"(a2), "=r"(a3) : "r"(aaddr));
#pragma unroll
        for (int jp = 0; jp < 8; jp++) {
            uint32_t b0, b1, b2, b3;
            uint32_t baddr = sb + HG_B + sw_off(jp * 16 + bn, ks * 2 + bkc);
            asm volatile("ldmatrix.sync.aligned.m8n8.x4.shared.b16 {%0,%1,%2,%3}, [%4];"
                         : "=r"(b0), "=r"(b1), "=r"(b2), "=r"(b3) : "r"(baddr));
            asm volatile(
                "mma.sync.aligned.m16n8k16.row.col.f32.bf16.bf16.f32 "
                "{%0,%1,%2,%3}, {%4,%5,%6,%7}, {%8,%9}, {%0,%1,%2,%3};"
                : "+f"(acc[2 * jp][0]), "+f"(acc[2 * jp][1]),
                  "+f"(acc[2 * jp][2]), "+f"(acc[2 * jp][3])
                : "r"(a0), "r"(a1), "r"(a2), "r"(a3), "r"(b0), "r"(b1));
            asm volatile(
                "mma.sync.aligned.m16n8k16.row.col.f32.bf16.bf16.f32 "
                "{%0,%1,%2,%3}, {%4,%5,%6,%7}, {%8,%9}, {%0,%1,%2,%3};"
                : "+f"(acc[2 * jp + 1][0]), "+f"(acc[2 * jp + 1][1]),
                  "+f"(acc[2 * jp + 1][2]), "+f"(acc[2 * jp + 1][3])
                : "r"(a0), "r"(a1), "r"(a2), "r"(a3), "r"(b2), "r"(b3));
        }
    }

    int g = lane >> 2, tq = lane & 3;
    int rA = row0 + warpRow + g;
    int rB = rA + 8;
    bool okA = rA < NN, okB = rB < NN;
#pragma unroll
    for (int j = 0; j < 16; j++) {
        int c = j * 8 + tq * 2;
        float bx = sBias[c], by = sBias[c + 1];
        float2 vA = make_float2(acc[j][0] + bx, acc[j][1] + by);
        float2 vB = make_float2(acc[j][2] + bx, acc[j][3] + by);
        if (grp == 0) {
            if (okA) *(float2*)&g_q[(size_t)rA * CC + c] = vA;
            if (okB) *(float2*)&g_q[(size_t)rB * CC + c] = vB;
        } else if (grp == 3) {
            if (okA) *(float2*)&g_s[(size_t)rA * CC + c] = vA;
            if (okB) *(float2*)&g_s[(size_t)rB * CC + c] = vB;
        } else {
            int off = (grp == 2) ? 128 : 0;
            if (okA) { __half2 h = __floats2half2_rn(vA.x, vA.y); *(__half2*)&g_kvh[(size_t)rA * 256 + off + c] = h; }
            if (okB) { __half2 h = __floats2half2_rn(vB.x, vB.y); *(__half2*)&g_kvh[(size_t)rB * 256 + off + c] = h; }
        }
    }
}

// ---------------- edge aggregation ----------------
// mode bit0: write fp32 h (pool input); bit1: write bf16 h (GEMM input, sel by outSel)
__device__ __forceinline__ float4 ld_kv4(const __half* base, int idx) {
    uint2 u = *(const uint2*)(base + idx);
    __half2 h0 = *(__half2*)&u.x;
    __half2 h1 = *(__half2*)&u.y;
    float2 f0 = __half22float2(h0);
    float2 f1 = __half22float2(h1);
    return make_float4(f0.x, f0.y, f1.x, f1.y);
}

__global__ __launch_bounds__(256) void k_agg(const float* __restrict__ We,
                                             int outSel, int mode) {
    __shared__ float sWe[384];
    for (int i = threadIdx.x; i < 384; i += 256) sWe[i] = We[i];
    __syncthreads();

    int node = blockIdx.x * 8 + (threadIdx.x >> 5);
    if (node >= NN) return;
    int lane = threadIdx.x & 31;

    float4 qv = *(const float4*)&g_q[(size_t)node * CC + lane * 4];

    float t0, t1, t2;
    {
        int c = lane * 4;
        t0 = sWe[c] * qv.x + sWe[c + 1] * qv.y + sWe[c + 2] * qv.z + sWe[c + 3] * qv.w;
        c += 128;
        t1 = sWe[c] * qv.x + sWe[c + 1] * qv.y + sWe[c + 2] * qv.z + sWe[c + 3] * qv.w;
        c += 128;
        t2 = sWe[c] * qv.x + sWe[c + 1] * qv.y + sWe[c + 2] * qv.z + sWe[c + 3] * qv.w;
#pragma unroll
        for (int o = 16; o > 0; o >>= 1) {
            t0 += __shfl_xor_sync(0xffffffffu, t0, o);
            t1 += __shfl_xor_sync(0xffffffffu, t1, o);
            t2 += __shfl_xor_sync(0xffffffffu, t2, o);
        }
    }

    float m = -CUDART_INF_F, den = 0.f;
    float4 acc = make_float4(0.f, 0.f, 0.f, 0.f);
    float s0 = 0.f, s1 = 0.f, s2 = 0.f;
    const float scale = 0.08838834764831845f;

    int beg = __ldg(&g_off[node]), end = __ldg(&g_off[node + 1]);
    int p = beg;
    for (; p + 2 <= end; p += 2) {
        int n0 = __ldg(&g_srcA[p]), n1 = __ldg(&g_srcA[p + 1]);
        float4 ea0 = g_eaC[p], ea1 = g_eaC[p + 1];
        const __half* b0 = &g_kvh[(size_t)n0 * 256];
        const __half* b1 = &g_kvh[(size_t)n1 * 256];
        float4 kv0 = ld_kv4(b0, lane * 4);
        float4 vv0 = ld_kv4(b0, 128 + lane * 4);
        float4 kv1 = ld_kv4(b1, lane * 4);
        float4 vv1 = ld_kv4(b1, 128 + lane * 4);
        float d0 = qv.x * kv0.x + qv.y * kv0.y + qv.z * kv0.z + qv.w * kv0.w;
        float d1 = qv.x * kv1.x + qv.y * kv1.y + qv.z * kv1.z + qv.w * kv1.w;
#pragma unroll
        for (int o = 16; o > 0; o >>= 1) {
            d0 += __shfl_xor_sync(0xffffffffu, d0, o);
            d1 += __shfl_xor_sync(0xffffffffu, d1, o);
        }
        float l0 = (d0 + ea0.x * t0 + ea0.y * t1 + ea0.z * t2) * scale;
        float l1 = (d1 + ea1.x * t0 + ea1.y * t1 + ea1.z * t2) * scale;
        float nm = fmaxf(m, fmaxf(l0, l1));
        float corr = __expf(m - nm);
        float w0 = __expf(l0 - nm);
        float w1 = __expf(l1 - nm);
        den = den * corr + w0 + w1;
        acc.x = acc.x * corr + w0 * vv0.x + w1 * vv1.x;
        acc.y = acc.y * corr + w0 * vv0.y + w1 * vv1.y;
        acc.z = acc.z * corr + w0 * vv0.z + w1 * vv1.z;
        acc.w = acc.w * corr + w0 * vv0.w + w1 * vv1.w;
        s0 = s0 * corr + w0 * ea0.x + w1 * ea1.x;
        s1 = s1 * corr + w0 * ea0.y + w1 * ea1.y;
        s2 = s2 * corr + w0 * ea0.z + w1 * ea1.z;
        m = nm;
    }
    if (p < end) {
        int n0 = __ldg(&g_srcA[p]);
        float4 ea0 = g_eaC[p];
        const __half* b0 = &g_kvh[(size_t)n0 * 256];
        float4 kv0 = ld_kv4(b0, lane * 4);
        float4 vv0 = ld_kv4(b0, 128 + lane * 4);
        float d0 = qv.x * kv0.x + qv.y * kv0.y + qv.z * kv0.z + qv.w * kv0.w;
#pragma unroll
        for (int o = 16; o > 0; o >>= 1) d0 += __shfl_xor_sync(0xffffffffu, d0, o);
        float l0 = (d0 + ea0.x * t0 + ea0.y * t1 + ea0.z * t2) * scale;
        float nm = fmaxf(m, l0);
        float corr = __expf(m - nm);
        float w0 = __expf(l0 - nm);
        den = den * corr + w0;
        acc.x = acc.x * corr + w0 * vv0.x;
        acc.y = acc.y * corr + w0 * vv0.y;
        acc.z = acc.z * corr + w0 * vv0.z;
        acc.w = acc.w * corr + w0 * vv0.w;
        s0 = s0 * corr + w0 * ea0.x;
        s1 = s1 * corr + w0 * ea0.y;
        s2 = s2 * corr + w0 * ea0.z;
        m = nm;
    }

    float inv = den > 0.f ? 1.f / den : 0.f;
    s0 *= inv; s1 *= inv; s2 *= inv;
    float4 skip = *(const float4*)&g_s[(size_t)node * CC + lane * 4];
    int c = lane * 4;
    float4 o;
    o.x = acc.x * inv + s0 * sWe[c + 0] + s1 * sWe[128 + c + 0] + s2 * sWe[256 + c + 0] + skip.x;
    o.y = acc.y * inv + s0 * sWe[c + 1] + s1 * sWe[128 + c + 1] + s2 * sWe[256 + c + 1] + skip.y;
    o.z = acc.z * inv + s0 * sWe[c + 2] + s1 * sWe[128 + c + 2] + s2 * sWe[256 + c + 2] + skip.z;
    o.w = acc.w * inv + s0 * sWe[c + 3] + s1 * sWe[128 + c + 3] + s2 * sWe[256 + c + 3] + skip.w;
    o.x = o.x > 0.f ? o.x : 0.01f * o.x;
    o.y = o.y > 0.f ? o.y : 0.01f * o.y;
    o.z = o.z > 0.f ? o.z : 0.01f * o.z;
    o.w = o.w > 0.f ? o.w : 0.01f * o.w;
    if (mode & 1)
        *(float4*)&g_hA[(size_t)node * CC + c] = o;
    if (mode & 2) {
        __nv_bfloat16* __restrict__ out16 = outSel ? g_h16B : g_h16A;
        __nv_bfloat162 p0 = __floats2bfloat162_rn(o.x, o.y);
        __nv_bfloat162 p1 = __floats2bfloat162_rn(o.z, o.w);
        uint2 u;
        u.x = *(unsigned int*)&p0;
        u.y = *(unsigned int*)&p1;
        *(uint2*)&out16[(size_t)node * CC + c] = u;
    }
}

// ---------------- pooling ----------------
__global__ void k_pool() {
    int g = blockIdx.x;
    int c = threadIdx.x;
    int s = g_gstart[g], e = g_gstart[g + 1];
    float acc = 0.f;
    for (int n = s; n < e; n++) acc += g_hA[(size_t)n * CC + c];
    g_pool[g * CC + c] = acc;
}

// ---------------- MLP head ----------------
__global__ void k_mlp1(const float* __restrict__ W, const float* __restrict__ b) {
    int idx = blockIdx.x * blockDim.x + threadIdx.x;
    if (idx >= GG * L0) return;
    int r = idx >> 9, c = idx & (L0 - 1);
    float s = b[c];
    for (int k = 0; k < CC; k++) s += g_pool[r * CC + k] * W[k * L0 + c];
    g_m1[idx] = s > 0.f ? s : 0.f;
}
__global__ void k_mlp2(const float* __restrict__ W, const float* __restrict__ b) {
    int idx = blockIdx.x * blockDim.x + threadIdx.x;
    if (idx >= GG * L1) return;
    int r = idx >> 8, c = idx & (L1 - 1);
    float s = b[c];
    for (int k = 0; k < L0; k++) s += g_m1[r * L0 + k] * W[k * L1 + c];
    g_m2[idx] = s > 0.f ? s : 0.f;
}
__global__ void k_mlp3(const float* __restrict__ W, const float* __restrict__ b,
                       float* __restrict__ out) {
    int idx = threadIdx.x;
    if (idx >= GG * 2) return;
    int r = idx >> 1, c = idx & 1;
    float s = b[c];
    for (int k = 0; k < L1; k++) s += g_m2[r * L1 + k] * W[k * 2 + c];
    out[idx] = s;
}

// ---------------- launch ----------------
extern "C" void kernel_launch(void* const* d_in, const int* in_sizes, int n_in,
                              void* d_out, int out_size) {
    const float* x     = (const float*)d_in[0];
    const int*   ei    = (const int*)d_in[1];
    const float* ea    = (const float*)d_in[2];
    const int*   batch = (const int*)d_in[3];
    const float* Wq0 = (const float*)d_in[4];  const float* bq0 = (const float*)d_in[5];
    const float* Wk0 = (const float*)d_in[6];  const float* bk0 = (const float*)d_in[7];
    const float* Wv0 = (const float*)d_in[8];  const float* bv0 = (const float*)d_in[9];
    const float* We0 = (const float*)d_in[10];
    const float* Ws0 = (const float*)d_in[11]; const float* bs0 = (const float*)d_in[12];
    const float* Wq1 = (const float*)d_in[13]; const float* bq1 = (const float*)d_in[14];
    const float* Wk1 = (const float*)d_in[15]; const float* bk1 = (const float*)d_in[16];
    const float* Wv1 = (const float*)d_in[17]; const float* bv1 = (const float*)d_in[18];
    const float* We1 = (const float*)d_in[19];
    const float* Ws1 = (const float*)d_in[20]; const float* bs1 = (const float*)d_in[21];
    const float* Wl0 = (const float*)d_in[22]; const float* bl0 = (const float*)d_in[23];
    const float* Wl1 = (const float*)d_in[24]; const float* bl1 = (const float*)d_in[25];
    const float* Wl2 = (const float*)d_in[26]; const float* bl2 = (const float*)d_in[27];
    float* out = (float*)d_out;

    cudaFuncSetAttribute(k_hgemm, cudaFuncAttributeMaxDynamicSharedMemorySize, HG_SMEM);

    // CSR build (g_cnt starts zero; k_scat self-cleans it each run)
    k_count<<<(EE + 255) / 256, 256>>>(ei);
    k_sum<<<SCAN_NBLK, SCAN_BLK>>>();
    k_scat<<<SCAN_NBLK, SCAN_BLK>>>(batch);
    k_prep<<<FILL_BLKS + G0_BLKS + WT_BLKS, 256>>>(ei, ea, x,
                                                   Wq0, bq0, Wk0, bk0, Wv0, bv0, Ws0, bs0,
                                                   Wq1, Wk1, Wv1, Ws1);

    dim3 hgGrid(4, (NN + 127) / 128);

    // layer 0 -> h16A only
    k_agg<<<(NN + 7) / 8, 256>>>(We0, 0, 2);
    // layer 1 (shared weights) -> h16B only
    k_hgemm<<<hgGrid, 256, HG_SMEM>>>(0, bq1, bk1, bv1, bs1);
    k_agg<<<(NN + 7) / 8, 256>>>(We1, 1, 2);
    // layer 2 (same weights) -> fp32 hA only (pool input)
    k_hgemm<<<hgGrid, 256, HG_SMEM>>>(1, bq1, bk1, bv1, bs1);
    k_agg<<<(NN + 7) / 8, 256>>>(We1, 0, 1);

    // pool + MLP head
    k_pool<<<GG, CC>>>();
    k_mlp1<<<(GG * L0 + 255) / 256, 256>>>(Wl0, bl0);
    k_mlp2<<<(GG * L1 + 255) / 256, 256>>>(Wl1, bl1);
    k_mlp3<<<1, 256>>>(Wl2, bl2, out);
}